// round 8
// baseline (speedup 1.0000x reference)
#include <cuda_runtime.h>
#include <cuda_fp16.h>
#include <cstdint>

// Submanifold sparse conv: rulebook gather -> per-offset 16x16 GEMV -> scatter-add.
// Quad-cooperative (4 lanes per rule), fp16 feature gather (1 sector/row, 2-SHFL
// exchanges), fp32 weights/accum/scatter. U=6 rule batching @ 3 blocks/SM.
// Prologue fuses f32->f16 feature convert with bias broadcast in one kernel.

constexpr int KOFF = 27;
constexpr int CIN  = 16;
constexpr int COUT = 16;
constexpr int U    = 6;                 // rules per lane-slot
constexpr int RPB  = 8 * 8 * U;         // rules per block = 384
constexpr int NMAX = 500000;            // active sites (problem-fixed)

// fp16 feature scratch: [N][16] halves = 16MB
__device__ __align__(16) __half g_feat_h[NMAX * CIN];

// Fused prologue: part A converts features f32->f16, part B writes bias to out.
__global__ void prologue_kernel(const float4* __restrict__ feat4,
                                float4* __restrict__ out4,
                                const float4* __restrict__ bias4,
                                int n8 /* N*16/8 */, int n4 /* N*4 */) {
    const int i = blockIdx.x * blockDim.x + threadIdx.x;
    if (i < n8) {
        const float4 a = feat4[2 * i + 0];
        const float4 b = feat4[2 * i + 1];
        __half2 h0 = __floats2half2_rn(a.x, a.y);
        __half2 h1 = __floats2half2_rn(a.z, a.w);
        __half2 h2 = __floats2half2_rn(b.x, b.y);
        __half2 h3 = __floats2half2_rn(b.z, b.w);
        uint4 packed;
        packed.x = *reinterpret_cast<unsigned*>(&h0);
        packed.y = *reinterpret_cast<unsigned*>(&h1);
        packed.z = *reinterpret_cast<unsigned*>(&h2);
        packed.w = *reinterpret_cast<unsigned*>(&h3);
        reinterpret_cast<uint4*>(g_feat_h)[i] = packed;
    }
    // bias part: reuse the same threads for the [0, n4) range (n4 = 2*n8)
    const int j0 = i * 2;
#pragma unroll
    for (int t = 0; t < 2; ++t) {
        const int j = j0 + t;
        if (j < n4) out4[j] = bias4[j & 3];
    }
}

__device__ __forceinline__ uint2 shfl_xor_u2(uint2 v, int mask) {
    uint2 r;
    r.x = __shfl_xor_sync(0xffffffffu, v.x, mask);
    r.y = __shfl_xor_sync(0xffffffffu, v.y, mask);
    return r;
}

__device__ __forceinline__ float4 h4_to_f4(uint2 v) {
    __half2 a = *reinterpret_cast<__half2*>(&v.x);
    __half2 b = *reinterpret_cast<__half2*>(&v.y);
    const float2 fa = __half22float2(a);
    const float2 fb = __half22float2(b);
    return make_float4(fa.x, fa.y, fb.x, fb.y);
}

__global__ void __launch_bounds__(256, 3)
subconv_kernel(const float4* __restrict__ weight4,  // [27*64] : [k][cin][j]
               const int*    __restrict__ rin,      // [27*R]
               const int*    __restrict__ rout,     // [27*R]
               float*        __restrict__ out,      // [N*16]
               int R) {
    // wsh[c*4 + j] = W[c][4j..4j+3] for this offset k
    __shared__ float4 wsh[CIN * 4];

    const int k = blockIdx.y;
    if (threadIdx.x < CIN * 4) {
        wsh[threadIdx.x] = weight4[k * (CIN * 4) + threadIdx.x];
    }
    __syncthreads();

    const uint2* __restrict__ feath2 = reinterpret_cast<const uint2*>(g_feat_h);

    const int lane = threadIdx.x & 31;
    const int warp = threadIdx.x >> 5;
    const int q    = lane & 3;    // this lane owns feature quad q and output quad q
    const int rs   = lane >> 2;   // rule slot (8 per warp)
    const int kbase = k * R;      // fits int32 (max 6.75M)
    const int rbase = blockIdx.x * RPB + warp * (8 * U) + rs;

    // ---- phase 1: all index loads in flight together ----
    int  ii[U], io[U];
    bool valid[U];
#pragma unroll
    for (int u = 0; u < U; ++u) {
        const int r = rbase + u * 8;
        valid[u] = (r < R);
        const int idx = valid[u] ? r : 0;
        ii[u] = rin[kbase + idx];
        io[u] = rout[kbase + idx];
    }

    // ---- phase 2: all gathers (fp16 row = 32B = 1 sector; quad lanes coalesce) ----
    uint2 v[U];
#pragma unroll
    for (int u = 0; u < U; ++u) {
        v[u] = feath2[ii[u] * 4 + q];   // int32 offsets (max 2M)
    }

    float4 acc[U];
#pragma unroll
    for (int u = 0; u < U; ++u) acc[u] = make_float4(0.f, 0.f, 0.f, 0.f);

    // ---- phase 3: g outer (share weight loads across rules), u inner ----
#pragma unroll
    for (int g = 0; g < 4; ++g) {
        const int qq = q ^ g;   // channel group applied this step
        const float4 w0 = wsh[(qq * 4 + 0) * 4 + q];
        const float4 w1 = wsh[(qq * 4 + 1) * 4 + q];
        const float4 w2 = wsh[(qq * 4 + 2) * 4 + q];
        const float4 w3 = wsh[(qq * 4 + 3) * 4 + q];

#pragma unroll
        for (int u = 0; u < U; ++u) {
            // Feature quad qq of rule u lives in lane^g (single-hop, 2x SHFL).
            const uint2 hv = (g == 0) ? v[u] : shfl_xor_u2(v[u], g);
            const float4 fg = h4_to_f4(hv);
            acc[u].x += fg.x * w0.x; acc[u].y += fg.x * w0.y;
            acc[u].z += fg.x * w0.z; acc[u].w += fg.x * w0.w;
            acc[u].x += fg.y * w1.x; acc[u].y += fg.y * w1.y;
            acc[u].z += fg.y * w1.z; acc[u].w += fg.y * w1.w;
            acc[u].x += fg.z * w2.x; acc[u].y += fg.z * w2.y;
            acc[u].z += fg.z * w2.z; acc[u].w += fg.z * w2.w;
            acc[u].x += fg.w * w3.x; acc[u].y += fg.w * w3.y;
            acc[u].z += fg.w * w3.z; acc[u].w += fg.w * w3.w;
        }
    }

    // ---- phase 4: coalesced scatter-RED (quad lanes hit one 64B row) ----
#pragma unroll
    for (int u = 0; u < U; ++u) {
        if (valid[u]) {
            float* op = out + (long)io[u] * COUT + q * 4;
            asm volatile("red.global.add.v4.f32 [%0], {%1,%2,%3,%4};"
                         :: "l"(op),
                            "f"(acc[u].x), "f"(acc[u].y),
                            "f"(acc[u].z), "f"(acc[u].w)
                         : "memory");
        }
    }
}

extern "C" void kernel_launch(void* const* d_in, const int* in_sizes, int n_in,
                              void* d_out, int out_size) {
    const float* features = (const float*)d_in[0];   // [N*16]
    const float* weight   = (const float*)d_in[1];   // [27*16*16]
    const float* bias     = (const float*)d_in[2];   // [16]
    const int*   rules_in = (const int*)d_in[3];     // [27*R]
    const int*   rules_out= (const int*)d_in[4];     // [27*R]
    float* out = (float*)d_out;                      // [N*16]

    const int N = in_sizes[0] / CIN;
    const int R = in_sizes[3] / KOFF;
    const int n4 = N * 4;
    const int n8 = N * CIN / 8;

    // 0) fused: features f32 -> f16 scratch  +  out = bias broadcast
    {
        const int threads = 256;
        const int blocks = (n8 + threads - 1) / threads;
        prologue_kernel<<<blocks, threads>>>(
            reinterpret_cast<const float4*>(features),
            (float4*)out, (const float4*)bias, n8, n4);
    }

    // 1) gather -> GEMV -> scatter-add; 384 rules per block
    {
        const int threads = 256;
        dim3 grid((R + RPB - 1) / RPB, KOFF);
        subconv_kernel<<<grid, threads>>>(
            reinterpret_cast<const float4*>(weight),
            rules_in, rules_out, out, R);
    }
}

// round 9
// speedup vs baseline: 1.0479x; 1.0479x over previous
#include <cuda_runtime.h>
#include <cuda_fp16.h>
#include <cstdint>

// Submanifold sparse conv: rulebook gather -> per-offset 16x16 GEMV -> scatter-add.
// Quad-cooperative (4 lanes per rule), fp16 feature gather (1 sector/row, 2-SHFL
// exchanges), fp32 weights/accum/scatter. U=6 rule batching @ 3 blocks/SM.
// Prologue fuses f32->f16 feature convert with bias broadcast in one kernel.

constexpr int KOFF = 27;
constexpr int CIN  = 16;
constexpr int COUT = 16;
constexpr int U    = 6;                 // rules per lane-slot
constexpr int RPB  = 8 * 8 * U;         // rules per block = 384
constexpr int NMAX = 500000;            // active sites (problem-fixed)

// fp16 feature scratch: [N][16] halves = 16MB
__device__ __align__(16) __half g_feat_h[NMAX * CIN];

// Fused prologue: part A converts features f32->f16, part B writes bias to out.
__global__ void prologue_kernel(const float4* __restrict__ feat4,
                                float4* __restrict__ out4,
                                const float4* __restrict__ bias4,
                                int n8 /* N*16/8 */, int n4 /* N*4 */) {
    const int i = blockIdx.x * blockDim.x + threadIdx.x;
    if (i < n8) {
        const float4 a = feat4[2 * i + 0];
        const float4 b = feat4[2 * i + 1];
        __half2 h0 = __floats2half2_rn(a.x, a.y);
        __half2 h1 = __floats2half2_rn(a.z, a.w);
        __half2 h2 = __floats2half2_rn(b.x, b.y);
        __half2 h3 = __floats2half2_rn(b.z, b.w);
        uint4 packed;
        packed.x = *reinterpret_cast<unsigned*>(&h0);
        packed.y = *reinterpret_cast<unsigned*>(&h1);
        packed.z = *reinterpret_cast<unsigned*>(&h2);
        packed.w = *reinterpret_cast<unsigned*>(&h3);
        reinterpret_cast<uint4*>(g_feat_h)[i] = packed;
    }
    // bias part: reuse the same threads for the [0, n4) range (n4 = 2*n8)
    const int j0 = i * 2;
#pragma unroll
    for (int t = 0; t < 2; ++t) {
        const int j = j0 + t;
        if (j < n4) out4[j] = bias4[j & 3];
    }
}

__device__ __forceinline__ uint2 shfl_xor_u2(uint2 v, int mask) {
    uint2 r;
    r.x = __shfl_xor_sync(0xffffffffu, v.x, mask);
    r.y = __shfl_xor_sync(0xffffffffu, v.y, mask);
    return r;
}

__device__ __forceinline__ float4 h4_to_f4(uint2 v) {
    __half2 a = *reinterpret_cast<__half2*>(&v.x);
    __half2 b = *reinterpret_cast<__half2*>(&v.y);
    const float2 fa = __half22float2(a);
    const float2 fb = __half22float2(b);
    return make_float4(fa.x, fa.y, fb.x, fb.y);
}

__global__ void __launch_bounds__(256, 3)
subconv_kernel(const float4* __restrict__ weight4,  // [27*64] : [k][cin][j]
               const int*    __restrict__ rin,      // [27*R]
               const int*    __restrict__ rout,     // [27*R]
               float*        __restrict__ out,      // [N*16]
               int R) {
    // wsh[c*4 + j] = W[c][4j..4j+3] for this offset k
    __shared__ float4 wsh[CIN * 4];

    const int k = blockIdx.y;
    if (threadIdx.x < CIN * 4) {
        wsh[threadIdx.x] = weight4[k * (CIN * 4) + threadIdx.x];
    }
    __syncthreads();

    const uint2* __restrict__ feath2 = reinterpret_cast<const uint2*>(g_feat_h);

    const int lane = threadIdx.x & 31;
    const int warp = threadIdx.x >> 5;
    const int q    = lane & 3;    // this lane owns feature quad q and output quad q
    const int rs   = lane >> 2;   // rule slot (8 per warp)
    const int kbase = k * R;      // fits int32 (max 6.75M)
    const int rbase = blockIdx.x * RPB + warp * (8 * U) + rs;

    // ---- phase 1: all index loads in flight together ----
    int  ii[U], io[U];
    bool valid[U];
#pragma unroll
    for (int u = 0; u < U; ++u) {
        const int r = rbase + u * 8;
        valid[u] = (r < R);
        const int idx = valid[u] ? r : 0;
        ii[u] = rin[kbase + idx];
        io[u] = rout[kbase + idx];
    }

    // ---- phase 2: all gathers (fp16 row = 32B = 1 sector; quad lanes coalesce) ----
    uint2 v[U];
#pragma unroll
    for (int u = 0; u < U; ++u) {
        v[u] = feath2[ii[u] * 4 + q];   // int32 offsets (max 2M)
    }

    float4 acc[U];
#pragma unroll
    for (int u = 0; u < U; ++u) acc[u] = make_float4(0.f, 0.f, 0.f, 0.f);

    // ---- phase 3: g outer (share weight loads across rules), u inner ----
#pragma unroll
    for (int g = 0; g < 4; ++g) {
        const int qq = q ^ g;   // channel group applied this step
        const float4 w0 = wsh[(qq * 4 + 0) * 4 + q];
        const float4 w1 = wsh[(qq * 4 + 1) * 4 + q];
        const float4 w2 = wsh[(qq * 4 + 2) * 4 + q];
        const float4 w3 = wsh[(qq * 4 + 3) * 4 + q];

#pragma unroll
        for (int u = 0; u < U; ++u) {
            // Feature quad qq of rule u lives in lane^g (single-hop, 2x SHFL).
            const uint2 hv = (g == 0) ? v[u] : shfl_xor_u2(v[u], g);
            const float4 fg = h4_to_f4(hv);
            acc[u].x += fg.x * w0.x; acc[u].y += fg.x * w0.y;
            acc[u].z += fg.x * w0.z; acc[u].w += fg.x * w0.w;
            acc[u].x += fg.y * w1.x; acc[u].y += fg.y * w1.y;
            acc[u].z += fg.y * w1.z; acc[u].w += fg.y * w1.w;
            acc[u].x += fg.z * w2.x; acc[u].y += fg.z * w2.y;
            acc[u].z += fg.z * w2.z; acc[u].w += fg.z * w2.w;
            acc[u].x += fg.w * w3.x; acc[u].y += fg.w * w3.y;
            acc[u].z += fg.w * w3.z; acc[u].w += fg.w * w3.w;
        }
    }

    // ---- phase 4: coalesced scatter-RED (quad lanes hit one 64B row) ----
#pragma unroll
    for (int u = 0; u < U; ++u) {
        if (valid[u]) {
            float* op = out + (long)io[u] * COUT + q * 4;
            asm volatile("red.global.add.v4.f32 [%0], {%1,%2,%3,%4};"
                         :: "l"(op),
                            "f"(acc[u].x), "f"(acc[u].y),
                            "f"(acc[u].z), "f"(acc[u].w)
                         : "memory");
        }
    }
}

extern "C" void kernel_launch(void* const* d_in, const int* in_sizes, int n_in,
                              void* d_out, int out_size) {
    const float* features = (const float*)d_in[0];   // [N*16]
    const float* weight   = (const float*)d_in[1];   // [27*16*16]
    const float* bias     = (const float*)d_in[2];   // [16]
    const int*   rules_in = (const int*)d_in[3];     // [27*R]
    const int*   rules_out= (const int*)d_in[4];     // [27*R]
    float* out = (float*)d_out;                      // [N*16]

    const int N = in_sizes[0] / CIN;
    const int R = in_sizes[3] / KOFF;
    const int n4 = N * 4;
    const int n8 = N * CIN / 8;

    // 0) fused: features f32 -> f16 scratch  +  out = bias broadcast
    {
        const int threads = 256;
        const int blocks = (n8 + threads - 1) / threads;
        prologue_kernel<<<blocks, threads>>>(
            reinterpret_cast<const float4*>(features),
            (float4*)out, (const float4*)bias, n8, n4);
    }

    // 1) gather -> GEMV -> scatter-add; 384 rules per block
    {
        const int threads = 256;
        dim3 grid((R + RPB - 1) / RPB, KOFF);
        subconv_kernel<<<grid, threads>>>(
            reinterpret_cast<const float4*>(weight),
            rules_in, rules_out, out, R);
    }
}

// round 10
// speedup vs baseline: 1.1055x; 1.0550x over previous
#include <cuda_runtime.h>
#include <cuda_fp16.h>
#include <cstdint>

// Submanifold sparse conv: rulebook gather -> per-offset 16x16 GEMV -> scatter-add.
// Tensor-core version: one warp processes 16 rules as an m16n8k16 A-fragment
// (rules x cin, fp16), two HMMA mma.sync ops produce all 16 outputs with fp32
// accumulation. Features stored in a fragment-permuted fp16 scratch so the
// gather is one coalesced LDG.64 per 8 rules. Weights fp16 (B fragments built
// once per block). Scatter via red.global.add.v2.f32 (sector-coalesced).

constexpr int KOFF = 27;
constexpr int CIN  = 16;
constexpr int COUT = 16;
constexpr int U    = 2;                  // 16-rule groups per warp iteration
constexpr int RPW  = 16 * U;             // rules per warp = 32
constexpr int RPB  = 8 * RPW;            // rules per block = 256
constexpr int NMAX = 500000;

// fp16 feature scratch, fragment-permuted rows: half order per row =
// [0,1,8,9, 2,3,10,11, 4,5,12,13, 6,7,14,15]  (lane m reads uint2 at m*8B:
// .x = cols {2m,2m+1} -> a0a1, .y = cols {8+2m,8+2m+1} -> a4a5)
__device__ __align__(16) __half g_feat_h[NMAX * CIN];

__device__ __forceinline__ unsigned packh2(float lo, float hi) {
    __half2 h = __floats2half2_rn(lo, hi);
    return *reinterpret_cast<unsigned*>(&h);
}

// Fused prologue: permuted f32->f16 feature convert + bias broadcast.
__global__ void prologue_kernel(const float4* __restrict__ feat4,
                                float4* __restrict__ out4,
                                const float4* __restrict__ bias4,
                                int N) {
    const int i = blockIdx.x * blockDim.x + threadIdx.x;
    if (i >= N) return;
    const float4 a = feat4[i * 4 + 0];   // cols 0-3
    const float4 b = feat4[i * 4 + 1];   // cols 4-7
    const float4 c = feat4[i * 4 + 2];   // cols 8-11
    const float4 d = feat4[i * 4 + 3];   // cols 12-15
    uint4 lo, hi;
    lo.x = packh2(a.x, a.y);  lo.y = packh2(c.x, c.y);   // [0,1, 8,9]
    lo.z = packh2(a.z, a.w);  lo.w = packh2(c.z, c.w);   // [2,3, 10,11]
    hi.x = packh2(b.x, b.y);  hi.y = packh2(d.x, d.y);   // [4,5, 12,13]
    hi.z = packh2(b.z, b.w);  hi.w = packh2(d.z, d.w);   // [6,7, 14,15]
    reinterpret_cast<uint4*>(g_feat_h)[i * 2 + 0] = lo;
    reinterpret_cast<uint4*>(g_feat_h)[i * 2 + 1] = hi;

    const float4 b0 = bias4[0], b1 = bias4[1], b2 = bias4[2], b3 = bias4[3];
    out4[i * 4 + 0] = b0;  out4[i * 4 + 1] = b1;
    out4[i * 4 + 2] = b2;  out4[i * 4 + 3] = b3;
}

__device__ __forceinline__ void mma16816(float d[4],
                                         unsigned a0, unsigned a1,
                                         unsigned a2, unsigned a3,
                                         unsigned b0, unsigned b1) {
    asm volatile(
        "mma.sync.aligned.m16n8k16.row.col.f32.f16.f16.f32 "
        "{%0,%1,%2,%3}, {%4,%5,%6,%7}, {%8,%9}, {%0,%1,%2,%3};"
        : "+f"(d[0]), "+f"(d[1]), "+f"(d[2]), "+f"(d[3])
        : "r"(a0), "r"(a1), "r"(a2), "r"(a3), "r"(b0), "r"(b1));
}

__device__ __forceinline__ void red2(float* p, float x, float y) {
    asm volatile("red.global.add.v2.f32 [%0], {%1,%2};"
                 :: "l"(p), "f"(x), "f"(y) : "memory");
}

__global__ void __launch_bounds__(256, 5)
subconv_kernel(const float* __restrict__ weight,   // [27*256] : [k][cin][cout]
               const int*   __restrict__ rin,      // [27*R]
               const int*   __restrict__ rout,     // [27*R]
               float*       __restrict__ out,      // [N*16]
               int R) {
    __shared__ float wsh[CIN * COUT];

    const int k = blockIdx.y;
    wsh[threadIdx.x] = weight[k * (CIN * COUT) + threadIdx.x];
    __syncthreads();

    const int lane = threadIdx.x & 31;
    const int warp = threadIdx.x >> 5;
    const int g    = lane >> 2;   // groupID: rule row within 16-rule tile
    const int m    = lane & 3;    // k-pair / col-pair selector

    // B fragments (built once; fp16 weights, fp32 accumulate in MMA).
    // b0: k = 2m,2m+1 ; b1: k = 8+2m,9+2m ; n = g (frag N0) or 8+g (frag N1)
    const unsigned b0n0 = packh2(wsh[(2 * m)     * 16 + g],     wsh[(2 * m + 1) * 16 + g]);
    const unsigned b1n0 = packh2(wsh[(8 + 2 * m) * 16 + g],     wsh[(9 + 2 * m) * 16 + g]);
    const unsigned b0n1 = packh2(wsh[(2 * m)     * 16 + 8 + g], wsh[(2 * m + 1) * 16 + 8 + g]);
    const unsigned b1n1 = packh2(wsh[(8 + 2 * m) * 16 + 8 + g], wsh[(9 + 2 * m) * 16 + 8 + g]);

    const int kbase = k * R;                       // <= 6.75M, int32 safe
    const int rb0   = blockIdx.x * RPB + warp * RPW;
    const uint2* __restrict__ fh = reinterpret_cast<const uint2*>(g_feat_h);

    // ---- phase 1: indices (rows g and g+8 of each 16-rule group) ----
    int  ilo[U], ihi[U], olo[U], ohi[U];
    bool vlo[U], vhi[U];
#pragma unroll
    for (int u = 0; u < U; ++u) {
        const int rl = rb0 + u * 16 + g;
        const int rh = rl + 8;
        vlo[u] = (rl < R);
        vhi[u] = (rh < R);
        const int cl = vlo[u] ? rl : 0;
        const int ch = vhi[u] ? rh : 0;
        ilo[u] = rin[kbase + cl];
        ihi[u] = rin[kbase + ch];
        olo[u] = rout[kbase + cl];
        ohi[u] = rout[kbase + ch];
    }

    // ---- phase 2: gathers (LDG.64; 4 lanes cover one 32B permuted row) ----
    uint2 alo[U], ahi[U];
#pragma unroll
    for (int u = 0; u < U; ++u) {
        alo[u] = fh[ilo[u] * 4 + m];
        ahi[u] = fh[ihi[u] * 4 + m];
    }

    // ---- phase 3: MMA + scatter ----
#pragma unroll
    for (int u = 0; u < U; ++u) {
        float d0[4] = {0.f, 0.f, 0.f, 0.f};   // outputs n = 0..7
        float d1[4] = {0.f, 0.f, 0.f, 0.f};   // outputs n = 8..15
        // A frag: a0 = (row g, k 2m..), a1 = (row g+8, ..), a2 = (row g, k 8+2m..), a3 = (row g+8, ..)
        mma16816(d0, alo[u].x, ahi[u].x, alo[u].y, ahi[u].y, b0n0, b1n0);
        mma16816(d1, alo[u].x, ahi[u].x, alo[u].y, ahi[u].y, b0n1, b1n1);

        // D frag: {d[0],d[1]} = (row g,   cols 2m,2m+1)
        //         {d[2],d[3]} = (row g+8, cols 2m,2m+1)
        if (vlo[u]) {
            float* p = out + (long)olo[u] * COUT;
            red2(p + 2 * m,     d0[0], d0[1]);
            red2(p + 8 + 2 * m, d1[0], d1[1]);
        }
        if (vhi[u]) {
            float* p = out + (long)ohi[u] * COUT;
            red2(p + 2 * m,     d0[2], d0[3]);
            red2(p + 8 + 2 * m, d1[2], d1[3]);
        }
    }
}

extern "C" void kernel_launch(void* const* d_in, const int* in_sizes, int n_in,
                              void* d_out, int out_size) {
    const float* features = (const float*)d_in[0];   // [N*16]
    const float* weight   = (const float*)d_in[1];   // [27*16*16]
    const float* bias     = (const float*)d_in[2];   // [16]
    const int*   rules_in = (const int*)d_in[3];     // [27*R]
    const int*   rules_out= (const int*)d_in[4];     // [27*R]
    float* out = (float*)d_out;                      // [N*16]

    const int N = in_sizes[0] / CIN;
    const int R = in_sizes[3] / KOFF;

    // 0) fused prologue: permuted f16 features + bias broadcast
    {
        const int threads = 256;
        const int blocks = (N + threads - 1) / threads;
        prologue_kernel<<<blocks, threads>>>(
            reinterpret_cast<const float4*>(features),
            (float4*)out, (const float4*)bias, N);
    }

    // 1) gather -> MMA -> scatter-add; 256 rules per block
    {
        const int threads = 256;
        dim3 grid((R + RPB - 1) / RPB, KOFF);
        subconv_kernel<<<grid, threads>>>(
            weight, rules_in, rules_out, out, R);
    }
}

// round 11
// speedup vs baseline: 1.2947x; 1.1711x over previous
#include <cuda_runtime.h>
#include <cuda_fp16.h>
#include <cstdint>

// Submanifold sparse conv: rulebook gather -> per-offset 16x16 GEMV -> scatter-add.
// Tensor-core version: one warp processes 16 rules as an m16n8k16 A-fragment
// (rules x cin, fp16); MMA0 computes EVEN output columns, MMA1 ODD columns, so
// each lane's D values are 4 contiguous floats -> single red.global.add.v4.f32
// per rule-row (halves REDG instruction count vs v2 pairs). Features in a
// fragment-permuted fp16 scratch (1 coalesced LDG.64 per 8 rules). fp32 accum.

constexpr int KOFF = 27;
constexpr int CIN  = 16;
constexpr int COUT = 16;
constexpr int U    = 2;                  // 16-rule groups per warp iteration
constexpr int RPW  = 16 * U;             // rules per warp = 32
constexpr int RPB  = 8 * RPW;            // rules per block = 256
constexpr int NMAX = 500000;

// fp16 feature scratch, fragment-permuted rows: half order per row =
// [0,1,8,9, 2,3,10,11, 4,5,12,13, 6,7,14,15]  (lane m reads uint2 at m*8B:
// .x = cols {2m,2m+1} -> a0/a1, .y = cols {8+2m,8+2m+1} -> a2/a3)
__device__ __align__(16) __half g_feat_h[NMAX * CIN];

__device__ __forceinline__ unsigned packh2(float lo, float hi) {
    __half2 h = __floats2half2_rn(lo, hi);
    return *reinterpret_cast<unsigned*>(&h);
}

// Fused prologue: permuted f32->f16 feature convert + bias broadcast.
__global__ void prologue_kernel(const float4* __restrict__ feat4,
                                float4* __restrict__ out4,
                                const float4* __restrict__ bias4,
                                int N) {
    const int i = blockIdx.x * blockDim.x + threadIdx.x;
    if (i >= N) return;
    const float4 a = feat4[i * 4 + 0];   // cols 0-3
    const float4 b = feat4[i * 4 + 1];   // cols 4-7
    const float4 c = feat4[i * 4 + 2];   // cols 8-11
    const float4 d = feat4[i * 4 + 3];   // cols 12-15
    uint4 lo, hi;
    lo.x = packh2(a.x, a.y);  lo.y = packh2(c.x, c.y);   // [0,1, 8,9]
    lo.z = packh2(a.z, a.w);  lo.w = packh2(c.z, c.w);   // [2,3, 10,11]
    hi.x = packh2(b.x, b.y);  hi.y = packh2(d.x, d.y);   // [4,5, 12,13]
    hi.z = packh2(b.z, b.w);  hi.w = packh2(d.z, d.w);   // [6,7, 14,15]
    reinterpret_cast<uint4*>(g_feat_h)[i * 2 + 0] = lo;
    reinterpret_cast<uint4*>(g_feat_h)[i * 2 + 1] = hi;

    const float4 b0 = bias4[0], b1 = bias4[1], b2 = bias4[2], b3 = bias4[3];
    out4[i * 4 + 0] = b0;  out4[i * 4 + 1] = b1;
    out4[i * 4 + 2] = b2;  out4[i * 4 + 3] = b3;
}

__device__ __forceinline__ void mma16816(float d[4],
                                         unsigned a0, unsigned a1,
                                         unsigned a2, unsigned a3,
                                         unsigned b0, unsigned b1) {
    asm volatile(
        "mma.sync.aligned.m16n8k16.row.col.f32.f16.f16.f32 "
        "{%0,%1,%2,%3}, {%4,%5,%6,%7}, {%8,%9}, {%0,%1,%2,%3};"
        : "+f"(d[0]), "+f"(d[1]), "+f"(d[2]), "+f"(d[3])
        : "r"(a0), "r"(a1), "r"(a2), "r"(a3), "r"(b0), "r"(b1));
}

__device__ __forceinline__ void red4(float* p, float x, float y, float z, float w) {
    asm volatile("red.global.add.v4.f32 [%0], {%1,%2,%3,%4};"
                 :: "l"(p), "f"(x), "f"(y), "f"(z), "f"(w) : "memory");
}

__global__ void __launch_bounds__(256, 5)
subconv_kernel(const float* __restrict__ weight,   // [27*256] : [k][cin][cout]
               const int*   __restrict__ rin,      // [27*R]
               const int*   __restrict__ rout,     // [27*R]
               float*       __restrict__ out,      // [N*16]
               int R) {
    __shared__ float wsh[CIN * COUT];

    const int k = blockIdx.y;
    wsh[threadIdx.x] = weight[k * (CIN * COUT) + threadIdx.x];
    __syncthreads();

    const int lane = threadIdx.x & 31;
    const int warp = threadIdx.x >> 5;
    const int g    = lane >> 2;   // groupID: rule row within 16-rule tile
    const int m    = lane & 3;    // k-pair / col-pair selector

    // B fragments. Column interleaving: MMA0's n-column j carries output
    // column 2j (EVEN), MMA1's n-column j carries output column 2j+1 (ODD).
    // Then lane (g,m) D values are outputs 4m..4m+3 (contiguous).
    // b0: k = 2m,2m+1 ; b1: k = 8+2m,9+2m ; this lane serves n = g.
    const unsigned b0e = packh2(wsh[(2 * m)     * 16 + 2 * g],     wsh[(2 * m + 1) * 16 + 2 * g]);
    const unsigned b1e = packh2(wsh[(8 + 2 * m) * 16 + 2 * g],     wsh[(9 + 2 * m) * 16 + 2 * g]);
    const unsigned b0o = packh2(wsh[(2 * m)     * 16 + 2 * g + 1], wsh[(2 * m + 1) * 16 + 2 * g + 1]);
    const unsigned b1o = packh2(wsh[(8 + 2 * m) * 16 + 2 * g + 1], wsh[(9 + 2 * m) * 16 + 2 * g + 1]);

    const int kbase = k * R;                       // <= 6.75M, int32 safe
    const int rb0   = blockIdx.x * RPB + warp * RPW;
    const uint2* __restrict__ fh = reinterpret_cast<const uint2*>(g_feat_h);

    // ---- phase 1: indices (rows g and g+8 of each 16-rule group) ----
    int  ilo[U], ihi[U], olo[U], ohi[U];
    bool vlo[U], vhi[U];
#pragma unroll
    for (int u = 0; u < U; ++u) {
        const int rl = rb0 + u * 16 + g;
        const int rh = rl + 8;
        vlo[u] = (rl < R);
        vhi[u] = (rh < R);
        const int cl = vlo[u] ? rl : 0;
        const int ch = vhi[u] ? rh : 0;
        ilo[u] = rin[kbase + cl];
        ihi[u] = rin[kbase + ch];
        olo[u] = rout[kbase + cl];
        ohi[u] = rout[kbase + ch];
    }

    // ---- phase 2: gathers (LDG.64; 4 lanes cover one 32B permuted row) ----
    uint2 alo[U], ahi[U];
#pragma unroll
    for (int u = 0; u < U; ++u) {
        alo[u] = fh[ilo[u] * 4 + m];
        ahi[u] = fh[ihi[u] * 4 + m];
    }

    // ---- phase 3: MMA + scatter ----
#pragma unroll
    for (int u = 0; u < U; ++u) {
        float de[4] = {0.f, 0.f, 0.f, 0.f};   // even output cols
        float dn[4] = {0.f, 0.f, 0.f, 0.f};   // odd output cols
        // A frag: a0 = (row g, k 2m..), a1 = (row g+8, ..),
        //         a2 = (row g, k 8+2m..), a3 = (row g+8, ..)
        mma16816(de, alo[u].x, ahi[u].x, alo[u].y, ahi[u].y, b0e, b1e);
        mma16816(dn, alo[u].x, ahi[u].x, alo[u].y, ahi[u].y, b0o, b1o);

        // Lane (g,m): row g cols {4m..4m+3} = {de[0],dn[0],de[1],dn[1]},
        //             row g+8 same cols     = {de[2],dn[2],de[3],dn[3]}.
        if (vlo[u]) {
            red4(out + (long)olo[u] * COUT + 4 * m, de[0], dn[0], de[1], dn[1]);
        }
        if (vhi[u]) {
            red4(out + (long)ohi[u] * COUT + 4 * m, de[2], dn[2], de[3], dn[3]);
        }
    }
}

extern "C" void kernel_launch(void* const* d_in, const int* in_sizes, int n_in,
                              void* d_out, int out_size) {
    const float* features = (const float*)d_in[0];   // [N*16]
    const float* weight   = (const float*)d_in[1];   // [27*16*16]
    const float* bias     = (const float*)d_in[2];   // [16]
    const int*   rules_in = (const int*)d_in[3];     // [27*R]
    const int*   rules_out= (const int*)d_in[4];     // [27*R]
    float* out = (float*)d_out;                      // [N*16]

    const int N = in_sizes[0] / CIN;
    const int R = in_sizes[3] / KOFF;

    // 0) fused prologue: permuted f16 features + bias broadcast
    {
        const int threads = 256;
        const int blocks = (N + threads - 1) / threads;
        prologue_kernel<<<blocks, threads>>>(
            reinterpret_cast<const float4*>(features),
            (float4*)out, (const float4*)bias, N);
    }

    // 1) gather -> MMA -> scatter-add; 256 rules per block
    {
        const int threads = 256;
        dim3 grid((R + RPB - 1) / RPB, KOFF);
        subconv_kernel<<<grid, threads>>>(
            weight, rules_in, rules_out, out, R);
    }
}

// round 12
// speedup vs baseline: 1.3256x; 1.0239x over previous
#include <cuda_runtime.h>
#include <cuda_fp16.h>
#include <cstdint>

// Submanifold sparse conv: rulebook gather -> per-offset 16x16 GEMV -> scatter-add.
// Tensor-core (m16n8k16) warp kernel, column-interleaved so each lane REDs one
// contiguous float4 per rule-row. R12: persistent 128-rule warps (4x32 loop,
// software-prefetched indices) amortize weight-smem load + B-fragment build 4x.

constexpr int KOFF = 27;
constexpr int CIN  = 16;
constexpr int COUT = 16;
constexpr int IT   = 4;                  // 32-rule iterations per warp
constexpr int RPW  = 32 * IT;            // rules per warp = 128
constexpr int RPB  = 8 * RPW;            // rules per block = 1024
constexpr int NMAX = 500000;

// fp16 feature scratch, fragment-permuted rows: half order per row =
// [0,1,8,9, 2,3,10,11, 4,5,12,13, 6,7,14,15]  (lane m reads uint2 at m*8B:
// .x = cols {2m,2m+1} -> a0/a1, .y = cols {8+2m,8+2m+1} -> a2/a3)
__device__ __align__(16) __half g_feat_h[NMAX * CIN];

__device__ __forceinline__ unsigned packh2(float lo, float hi) {
    __half2 h = __floats2half2_rn(lo, hi);
    return *reinterpret_cast<unsigned*>(&h);
}

// Fused prologue: permuted f32->f16 feature convert + bias broadcast.
__global__ void prologue_kernel(const float4* __restrict__ feat4,
                                float4* __restrict__ out4,
                                const float4* __restrict__ bias4,
                                int N) {
    const int i = blockIdx.x * blockDim.x + threadIdx.x;
    if (i >= N) return;
    const float4 a = feat4[i * 4 + 0];   // cols 0-3
    const float4 b = feat4[i * 4 + 1];   // cols 4-7
    const float4 c = feat4[i * 4 + 2];   // cols 8-11
    const float4 d = feat4[i * 4 + 3];   // cols 12-15
    uint4 lo, hi;
    lo.x = packh2(a.x, a.y);  lo.y = packh2(c.x, c.y);   // [0,1, 8,9]
    lo.z = packh2(a.z, a.w);  lo.w = packh2(c.z, c.w);   // [2,3, 10,11]
    hi.x = packh2(b.x, b.y);  hi.y = packh2(d.x, d.y);   // [4,5, 12,13]
    hi.z = packh2(b.z, b.w);  hi.w = packh2(d.z, d.w);   // [6,7, 14,15]
    reinterpret_cast<uint4*>(g_feat_h)[i * 2 + 0] = lo;
    reinterpret_cast<uint4*>(g_feat_h)[i * 2 + 1] = hi;

    const float4 b0 = bias4[0], b1 = bias4[1], b2 = bias4[2], b3 = bias4[3];
    out4[i * 4 + 0] = b0;  out4[i * 4 + 1] = b1;
    out4[i * 4 + 2] = b2;  out4[i * 4 + 3] = b3;
}

__device__ __forceinline__ void mma16816(float d[4],
                                         unsigned a0, unsigned a1,
                                         unsigned a2, unsigned a3,
                                         unsigned b0, unsigned b1) {
    asm volatile(
        "mma.sync.aligned.m16n8k16.row.col.f32.f16.f16.f32 "
        "{%0,%1,%2,%3}, {%4,%5,%6,%7}, {%8,%9}, {%0,%1,%2,%3};"
        : "+f"(d[0]), "+f"(d[1]), "+f"(d[2]), "+f"(d[3])
        : "r"(a0), "r"(a1), "r"(a2), "r"(a3), "r"(b0), "r"(b1));
}

__device__ __forceinline__ void red4(float* p, float x, float y, float z, float w) {
    asm volatile("red.global.add.v4.f32 [%0], {%1,%2,%3,%4};"
                 :: "l"(p), "f"(x), "f"(y), "f"(z), "f"(w) : "memory");
}

__global__ void __launch_bounds__(256, 4)
subconv_kernel(const float* __restrict__ weight,   // [27*256] : [k][cin][cout]
               const int*   __restrict__ rin,      // [27*R]
               const int*   __restrict__ rout,     // [27*R]
               float*       __restrict__ out,      // [N*16]
               int R) {
    __shared__ float wsh[CIN * COUT];

    const int k = blockIdx.y;
    wsh[threadIdx.x] = weight[k * (CIN * COUT) + threadIdx.x];
    __syncthreads();

    const int lane = threadIdx.x & 31;
    const int warp = threadIdx.x >> 5;
    const int g    = lane >> 2;   // groupID: rule row within 16-rule tile
    const int m    = lane & 3;    // k-pair / col selector

    // B fragments (built once per warp, reused for 128 rules).
    // Column interleaving: MMA-even's n-column j = output col 2j, MMA-odd's = 2j+1,
    // so lane (g,m) D values are outputs 4m..4m+3 (contiguous float4).
    const unsigned b0e = packh2(wsh[(2 * m)     * 16 + 2 * g],     wsh[(2 * m + 1) * 16 + 2 * g]);
    const unsigned b1e = packh2(wsh[(8 + 2 * m) * 16 + 2 * g],     wsh[(9 + 2 * m) * 16 + 2 * g]);
    const unsigned b0o = packh2(wsh[(2 * m)     * 16 + 2 * g + 1], wsh[(2 * m + 1) * 16 + 2 * g + 1]);
    const unsigned b1o = packh2(wsh[(8 + 2 * m) * 16 + 2 * g + 1], wsh[(9 + 2 * m) * 16 + 2 * g + 1]);

    const int kbase = k * R;                       // <= 6.75M, int32 safe
    const int rb0   = blockIdx.x * RPB + warp * RPW;
    const uint2* __restrict__ fh = reinterpret_cast<const uint2*>(g_feat_h);

    // ---- prefetch indices for iteration 0 (rows g, g+8 of 2 x 16-rule groups) ----
    int  nilo[2], nihi[2], nolo[2], nohi[2];
#pragma unroll
    for (int u = 0; u < 2; ++u) {
        const int rl = rb0 + u * 16 + g;
        const int rh = rl + 8;
        const int cl = (rl < R) ? rl : 0;
        const int ch = (rh < R) ? rh : 0;
        nilo[u] = rin[kbase + cl];
        nihi[u] = rin[kbase + ch];
        nolo[u] = rout[kbase + cl];
        nohi[u] = rout[kbase + ch];
    }

#pragma unroll
    for (int it = 0; it < IT; ++it) {
        const int base_it = rb0 + it * 32;
        int ilo[2], ihi[2], olo[2], ohi[2];
#pragma unroll
        for (int u = 0; u < 2; ++u) {
            ilo[u] = nilo[u]; ihi[u] = nihi[u];
            olo[u] = nolo[u]; ohi[u] = nohi[u];
        }

        // ---- gathers (LDG.64; 4 lanes cover one 32B permuted row) ----
        uint2 alo[2], ahi[2];
#pragma unroll
        for (int u = 0; u < 2; ++u) {
            alo[u] = fh[ilo[u] * 4 + m];
            ahi[u] = fh[ihi[u] * 4 + m];
        }

        // ---- prefetch next iteration's indices (overlaps gather latency) ----
        if (it + 1 < IT) {
            const int nb = base_it + 32;
#pragma unroll
            for (int u = 0; u < 2; ++u) {
                const int rl = nb + u * 16 + g;
                const int rh = rl + 8;
                const int cl = (rl < R) ? rl : 0;
                const int ch = (rh < R) ? rh : 0;
                nilo[u] = rin[kbase + cl];
                nihi[u] = rin[kbase + ch];
                nolo[u] = rout[kbase + cl];
                nohi[u] = rout[kbase + ch];
            }
        }

        // ---- MMA + scatter ----
#pragma unroll
        for (int u = 0; u < 2; ++u) {
            float de[4] = {0.f, 0.f, 0.f, 0.f};   // even output cols
            float dn[4] = {0.f, 0.f, 0.f, 0.f};   // odd output cols
            mma16816(de, alo[u].x, ahi[u].x, alo[u].y, ahi[u].y, b0e, b1e);
            mma16816(dn, alo[u].x, ahi[u].x, alo[u].y, ahi[u].y, b0o, b1o);

            const int rl = base_it + u * 16 + g;
            // Lane (g,m): row g cols {4m..4m+3} = {de[0],dn[0],de[1],dn[1]},
            //             row g+8 same cols     = {de[2],dn[2],de[3],dn[3]}.
            if (rl < R) {
                red4(out + (long)olo[u] * COUT + 4 * m, de[0], dn[0], de[1], dn[1]);
            }
            if (rl + 8 < R) {
                red4(out + (long)ohi[u] * COUT + 4 * m, de[2], dn[2], de[3], dn[3]);
            }
        }
    }
}

extern "C" void kernel_launch(void* const* d_in, const int* in_sizes, int n_in,
                              void* d_out, int out_size) {
    const float* features = (const float*)d_in[0];   // [N*16]
    const float* weight   = (const float*)d_in[1];   // [27*16*16]
    const float* bias     = (const float*)d_in[2];   // [16]
    const int*   rules_in = (const int*)d_in[3];     // [27*R]
    const int*   rules_out= (const int*)d_in[4];     // [27*R]
    float* out = (float*)d_out;                      // [N*16]

    const int N = in_sizes[0] / CIN;
    const int R = in_sizes[3] / KOFF;

    // 0) fused prologue: permuted f16 features + bias broadcast
    {
        const int threads = 256;
        const int blocks = (N + threads - 1) / threads;
        prologue_kernel<<<blocks, threads>>>(
            reinterpret_cast<const float4*>(features),
            (float4*)out, (const float4*)bias, N);
    }

    // 1) gather -> MMA -> scatter-add; 1024 rules per block
    {
        const int threads = 256;
        dim3 grid((R + RPB - 1) / RPB, KOFF);
        subconv_kernel<<<grid, threads>>>(
            weight, rules_in, rules_out, out, R);
    }
}

// round 16
// speedup vs baseline: 1.3860x; 1.0456x over previous
#include <cuda_runtime.h>
#include <cuda_fp16.h>
#include <cstdint>

// Submanifold sparse conv: rulebook gather -> per-offset 16x16 GEMV -> scatter-add.
// Tensor-core (m16n8k16) warp kernel, column-interleaved so each lane REDs one
// contiguous float4 per rule-row (instruction-floor scatter). R16: coalesced
// index loads (2 LDG.32 per 32 rules instead of 8 redundant ones) with SHFL
// distribution, and 4 blocks/SM occupancy.

constexpr int KOFF = 27;
constexpr int CIN  = 16;
constexpr int COUT = 16;
constexpr int IT   = 4;                  // 32-rule iterations per warp
constexpr int RPW  = 32 * IT;            // rules per warp = 128
constexpr int RPB  = 8 * RPW;            // rules per block = 1024
constexpr int NMAX = 500000;

// fp16 feature scratch, fragment-permuted rows: half order per row =
// [0,1,8,9, 2,3,10,11, 4,5,12,13, 6,7,14,15]  (lane m reads uint2 at m*8B:
// .x = cols {2m,2m+1} -> a0/a1, .y = cols {8+2m,8+2m+1} -> a2/a3)
__device__ __align__(16) __half g_feat_h[NMAX * CIN];

__device__ __forceinline__ unsigned packh2(float lo, float hi) {
    __half2 h = __floats2half2_rn(lo, hi);
    return *reinterpret_cast<unsigned*>(&h);
}

// Fused prologue: permuted f32->f16 feature convert + bias broadcast.
__global__ void prologue_kernel(const float4* __restrict__ feat4,
                                float4* __restrict__ out4,
                                const float4* __restrict__ bias4,
                                int N) {
    const int i = blockIdx.x * blockDim.x + threadIdx.x;
    if (i >= N) return;
    const float4 a = feat4[i * 4 + 0];   // cols 0-3
    const float4 b = feat4[i * 4 + 1];   // cols 4-7
    const float4 c = feat4[i * 4 + 2];   // cols 8-11
    const float4 d = feat4[i * 4 + 3];   // cols 12-15
    uint4 lo, hi;
    lo.x = packh2(a.x, a.y);  lo.y = packh2(c.x, c.y);   // [0,1, 8,9]
    lo.z = packh2(a.z, a.w);  lo.w = packh2(c.z, c.w);   // [2,3, 10,11]
    hi.x = packh2(b.x, b.y);  hi.y = packh2(d.x, d.y);   // [4,5, 12,13]
    hi.z = packh2(b.z, b.w);  hi.w = packh2(d.z, d.w);   // [6,7, 14,15]
    reinterpret_cast<uint4*>(g_feat_h)[i * 2 + 0] = lo;
    reinterpret_cast<uint4*>(g_feat_h)[i * 2 + 1] = hi;

    const float4 b0 = bias4[0], b1 = bias4[1], b2 = bias4[2], b3 = bias4[3];
    out4[i * 4 + 0] = b0;  out4[i * 4 + 1] = b1;
    out4[i * 4 + 2] = b2;  out4[i * 4 + 3] = b3;
}

__device__ __forceinline__ void mma16816(float d[4],
                                         unsigned a0, unsigned a1,
                                         unsigned a2, unsigned a3,
                                         unsigned b0, unsigned b1) {
    asm volatile(
        "mma.sync.aligned.m16n8k16.row.col.f32.f16.f16.f32 "
        "{%0,%1,%2,%3}, {%4,%5,%6,%7}, {%8,%9}, {%0,%1,%2,%3};"
        : "+f"(d[0]), "+f"(d[1]), "+f"(d[2]), "+f"(d[3])
        : "r"(a0), "r"(a1), "r"(a2), "r"(a3), "r"(b0), "r"(b1));
}

__device__ __forceinline__ void red4(float* p, float x, float y, float z, float w) {
    asm volatile("red.global.add.v4.f32 [%0], {%1,%2,%3,%4};"
                 :: "l"(p), "f"(x), "f"(y), "f"(z), "f"(w) : "memory");
}

__global__ void __launch_bounds__(256, 4)
subconv_kernel(const float* __restrict__ weight,   // [27*256] : [k][cin][cout]
               const int*   __restrict__ rin,      // [27*R]
               const int*   __restrict__ rout,     // [27*R]
               float*       __restrict__ out,      // [N*16]
               int R) {
    __shared__ float wsh[CIN * COUT];

    const int k = blockIdx.y;
    wsh[threadIdx.x] = weight[k * (CIN * COUT) + threadIdx.x];
    __syncthreads();

    const int lane = threadIdx.x & 31;
    const int warp = threadIdx.x >> 5;
    const int g    = lane >> 2;   // groupID: rule row within 16-rule tile
    const int m    = lane & 3;    // k-pair / col selector

    // B fragments (built once per warp, reused for 128 rules).
    // Column interleaving: MMA-even's n-column j = output col 2j, MMA-odd's = 2j+1,
    // so lane (g,m) D values are outputs 4m..4m+3 (contiguous float4).
    const unsigned b0e = packh2(wsh[(2 * m)     * 16 + 2 * g],     wsh[(2 * m + 1) * 16 + 2 * g]);
    const unsigned b1e = packh2(wsh[(8 + 2 * m) * 16 + 2 * g],     wsh[(9 + 2 * m) * 16 + 2 * g]);
    const unsigned b0o = packh2(wsh[(2 * m)     * 16 + 2 * g + 1], wsh[(2 * m + 1) * 16 + 2 * g + 1]);
    const unsigned b1o = packh2(wsh[(8 + 2 * m) * 16 + 2 * g + 1], wsh[(9 + 2 * m) * 16 + 2 * g + 1]);

    const int kbase = k * R;                       // <= 6.75M, int32 safe
    const int rb0   = blockIdx.x * RPB + warp * RPW;
    const uint2* __restrict__ fh = reinterpret_cast<const uint2*>(g_feat_h);

    // ---- coalesced index loads for iteration 0: lane holds position rb0+lane ----
    int rin_v, rout_v;
    {
        const int p = rb0 + lane;
        const int c = (p < R) ? p : 0;
        rin_v  = rin[kbase + c];
        rout_v = rout[kbase + c];
    }

#pragma unroll
    for (int it = 0; it < IT; ++it) {
        const int base_it = rb0 + it * 32;

        // ---- distribute indices within the warp (replaces 8 redundant LDGs) ----
        // group u rows: positions base_it + u*16 + g (lo) and +8 (hi)
        const int ilo0 = __shfl_sync(0xffffffffu, rin_v,  g);
        const int ihi0 = __shfl_sync(0xffffffffu, rin_v,  g + 8);
        const int ilo1 = __shfl_sync(0xffffffffu, rin_v,  g + 16);
        const int ihi1 = __shfl_sync(0xffffffffu, rin_v,  g + 24);
        const int olo0 = __shfl_sync(0xffffffffu, rout_v, g);
        const int ohi0 = __shfl_sync(0xffffffffu, rout_v, g + 8);
        const int olo1 = __shfl_sync(0xffffffffu, rout_v, g + 16);
        const int ohi1 = __shfl_sync(0xffffffffu, rout_v, g + 24);

        // ---- gathers (LDG.64; 4 lanes cover one 32B permuted row) ----
        const uint2 alo0 = fh[ilo0 * 4 + m];
        const uint2 ahi0 = fh[ihi0 * 4 + m];
        const uint2 alo1 = fh[ilo1 * 4 + m];
        const uint2 ahi1 = fh[ihi1 * 4 + m];

        // ---- coalesced prefetch of next iteration's indices ----
        if (it + 1 < IT) {
            const int p = base_it + 32 + lane;
            const int c = (p < R) ? p : 0;
            rin_v  = rin[kbase + c];
            rout_v = rout[kbase + c];
        }

        // ---- MMA + scatter, group u = 0 ----
        {
            float de[4] = {0.f, 0.f, 0.f, 0.f};
            float dn[4] = {0.f, 0.f, 0.f, 0.f};
            mma16816(de, alo0.x, ahi0.x, alo0.y, ahi0.y, b0e, b1e);
            mma16816(dn, alo0.x, ahi0.x, alo0.y, ahi0.y, b0o, b1o);
            const int rl = base_it + g;
            if (rl < R) {
                red4(out + (long)olo0 * COUT + 4 * m, de[0], dn[0], de[1], dn[1]);
            }
            if (rl + 8 < R) {
                red4(out + (long)ohi0 * COUT + 4 * m, de[2], dn[2], de[3], dn[3]);
            }
        }
        // ---- MMA + scatter, group u = 1 ----
        {
            float de[4] = {0.f, 0.f, 0.f, 0.f};
            float dn[4] = {0.f, 0.f, 0.f, 0.f};
            mma16816(de, alo1.x, ahi1.x, alo1.y, ahi1.y, b0e, b1e);
            mma16816(dn, alo1.x, ahi1.x, alo1.y, ahi1.y, b0o, b1o);
            const int rl = base_it + 16 + g;
            if (rl < R) {
                red4(out + (long)olo1 * COUT + 4 * m, de[0], dn[0], de[1], dn[1]);
            }
            if (rl + 8 < R) {
                red4(out + (long)ohi1 * COUT + 4 * m, de[2], dn[2], de[3], dn[3]);
            }
        }
    }
}

extern "C" void kernel_launch(void* const* d_in, const int* in_sizes, int n_in,
                              void* d_out, int out_size) {
    const float* features = (const float*)d_in[0];   // [N*16]
    const float* weight   = (const float*)d_in[1];   // [27*16*16]
    const float* bias     = (const float*)d_in[2];   // [16]
    const int*   rules_in = (const int*)d_in[3];     // [27*R]
    const int*   rules_out= (const int*)d_in[4];     // [27*R]
    float* out = (float*)d_out;                      // [N*16]

    const int N = in_sizes[0] / CIN;
    const int R = in_sizes[3] / KOFF;

    // 0) fused prologue: permuted f16 features + bias broadcast
    {
        const int threads = 256;
        const int blocks = (N + threads - 1) / threads;
        prologue_kernel<<<blocks, threads>>>(
            reinterpret_cast<const float4*>(features),
            (float4*)out, (const float4*)bias, N);
    }

    // 1) gather -> MMA -> scatter-add; 1024 rules per block
    {
        const int threads = 256;
        dim3 grid((R + RPB - 1) / RPB, KOFF);
        subconv_kernel<<<grid, threads>>>(
            weight, rules_in, rules_out, out, R);
    }
}